// round 17
// baseline (speedup 1.0000x reference)
#include <cuda_runtime.h>
#include <cuda_fp16.h>
#include <cstdint>

// Problem constants (fixed by setup_inputs)
#define B_WIN   4096
#define NTOK    49
#define C_DIM   192
#define NHEAD   6
#define DHEAD   32
#define NWIN    64
#define M_TOTAL (B_WIN * NTOK)     // 200704 = 128 * 1568
#define QKV_N   576
#define KDIM    192

// Scratch (__device__ globals: allocation-guard-safe)
__device__ unsigned short g_x_h[(size_t)M_TOTAL * KDIM];     // x in fp16
__device__ unsigned short g_qkv_h[(size_t)M_TOTAL * QKV_N];  // qkv in fp16
__device__ unsigned short g_att_h[(size_t)M_TOTAL * C_DIM];  // attn out fp16
__device__ unsigned short g_wqkvT_h[QKV_N * KDIM];           // w_qkv^T fp16 [N][K]
__device__ unsigned short g_wprojT_h[C_DIM * KDIM];          // w_proj^T fp16 [N][K]

__device__ __forceinline__ uint32_t packh2(float lo, float hi) {
    uint32_t r;
    asm("cvt.rn.f16x2.f32 %0, %1, %2;" : "=r"(r) : "f"(hi), "f"(lo));
    return r;
}

__device__ __forceinline__ uint32_t smem_u32(const void* p) {
    uint32_t a;
    asm("{ .reg .u64 t; cvta.to.shared.u64 t, %1; cvt.u32.u64 %0, t; }"
        : "=r"(a) : "l"(p));
    return a;
}

__device__ __forceinline__ void mma_f16(float* c, const uint32_t* a, const uint32_t* b) {
    asm volatile(
        "mma.sync.aligned.m16n8k16.row.col.f32.f16.f16.f32 "
        "{%0,%1,%2,%3}, {%4,%5,%6,%7}, {%8,%9}, {%0,%1,%2,%3};"
        : "+f"(c[0]), "+f"(c[1]), "+f"(c[2]), "+f"(c[3])
        : "r"(a[0]), "r"(a[1]), "r"(a[2]), "r"(a[3]), "r"(b[0]), "r"(b[1]));
}

#define LDSM_X4(r0, r1, r2, r3, addr) \
    asm volatile("ldmatrix.sync.aligned.m8n8.x4.shared.b16 {%0,%1,%2,%3}, [%4];" \
        : "=r"(r0), "=r"(r1), "=r"(r2), "=r"(r3) : "r"(addr))

#define CP_ASYNC16(dst, src) \
    asm volatile("cp.async.cg.shared.global [%0], [%1], 16;" \
        :: "r"(dst), "l"(src))
#define CP_COMMIT() asm volatile("cp.async.commit_group;")
#define CP_WAIT(n)  asm volatile("cp.async.wait_group %0;" :: "n"(n))

__device__ __forceinline__ void store2(float* C, size_t idx, float a, float b) {
    *reinterpret_cast<float2*>(C + idx) = make_float2(a, b);
}
__device__ __forceinline__ void store2(__half* C, size_t idx, float a, float b) {
    *reinterpret_cast<uint32_t*>(C + idx) = packh2(a, b);
}

// ---------------------------------------------------------------------------
// fp16 cp.async + ldmatrix GEMM v3: CTA 128x64 (R13-validated warp 32x32
// fragment maps), BK=64 halves, 2 smem stages rotating over 3 k-tiles.
// 48 KB smem -> 4 CTAs/SM.
// ---------------------------------------------------------------------------
#define BM 128
#define BN 64
#define BKH 64
#define STG_BYTES 24576                 // A 16384 + B 8192
#define GEMM_SMEM (2 * STG_BYTES)       // 49152

__device__ __forceinline__ void copy_tile(uint32_t sdst, const __half* A,
                                          const __half* WT, int m0, int n0,
                                          int t, int tid)
{
    const int k0 = t * BKH;
#pragma unroll
    for (int j = 0; j < 4; j++) {           // A: 128 rows x 8 chunks
        const int f = tid + j * 256;
        const int r = f >> 3, c = f & 7;
        CP_ASYNC16(sdst + r * 128 + ((c ^ (r & 7)) << 4),
                   A + (size_t)(m0 + r) * KDIM + k0 + c * 8);
    }
#pragma unroll
    for (int j = 0; j < 2; j++) {           // B: 64 n-rows x 8 chunks
        const int f = tid + j * 256;
        const int r = f >> 3, c = f & 7;
        CP_ASYNC16(sdst + 16384 + r * 128 + ((c ^ (r & 7)) << 4),
                   WT + (size_t)(n0 + r) * KDIM + k0 + c * 8);
    }
}

__device__ __forceinline__ void compute_tile(uint32_t sa, uint32_t sb,
                                             float acc[2][4][4],
                                             int wm, int wn, int lane)
{
    const int rAl = ((lane >> 3) & 1) * 8 + (lane & 7);
    const int cA  = lane >> 4;
    const int rBl = ((lane >> 4) & 1) * 8 + (lane & 7);
    const int cB  = (lane >> 3) & 1;
#pragma unroll
    for (int ks = 0; ks < 4; ks++) {
        uint32_t a[2][4], bb[4][2];
#pragma unroll
        for (int mt = 0; mt < 2; mt++) {
            const int r = wm * 32 + mt * 16 + rAl;
            const uint32_t ad = sa + r * 128 + (((2 * ks + cA) ^ (r & 7)) << 4);
            LDSM_X4(a[mt][0], a[mt][1], a[mt][2], a[mt][3], ad);
        }
#pragma unroll
        for (int p = 0; p < 2; p++) {
            const int r = wn * 32 + p * 16 + rBl;
            const uint32_t ad = sb + r * 128 + (((2 * ks + cB) ^ (r & 7)) << 4);
            uint32_t r0, r1, r2, r3;
            LDSM_X4(r0, r1, r2, r3, ad);
            bb[2 * p][0] = r0;  bb[2 * p][1] = r1;
            bb[2 * p + 1][0] = r2;  bb[2 * p + 1][1] = r3;
        }
#pragma unroll
        for (int mt = 0; mt < 2; mt++)
#pragma unroll
            for (int nt = 0; nt < 4; nt++)
                mma_f16(acc[mt][nt], a[mt], bb[nt]);
    }
}

template<typename TOUT>
__global__ __launch_bounds__(256, 4)
void mma_gemm(const __half* __restrict__ A, const __half* __restrict__ WT,
              TOUT* __restrict__ C, const float* __restrict__ bias, int N)
{
    extern __shared__ __align__(16) char dsm[];
    const uint32_t sb0 = smem_u32(dsm);
    const uint32_t sb1 = sb0 + STG_BYTES;

    const int tid  = threadIdx.x;
    const int wid  = tid >> 5;
    const int lane = tid & 31;
    const int grp  = lane >> 2;
    const int quad = lane & 3;
    const int wm   = wid & 3;        // 4 m-warps (32 rows each)
    const int wn   = wid >> 2;       // 2 n-warps (32 cols each)
    const int m0   = blockIdx.y * BM;
    const int n0   = blockIdx.x * BN;

    float acc[2][4][4];
#pragma unroll
    for (int mt = 0; mt < 2; mt++)
#pragma unroll
        for (int nt = 0; nt < 4; nt++)
#pragma unroll
            for (int r = 0; r < 4; r++) acc[mt][nt][r] = 0.0f;

    copy_tile(sb0, A, WT, m0, n0, 0, tid); CP_COMMIT();
    copy_tile(sb1, A, WT, m0, n0, 1, tid); CP_COMMIT();

    CP_WAIT(1); __syncthreads();
    compute_tile(sb0, sb0 + 16384, acc, wm, wn, lane);
    __syncthreads();
    copy_tile(sb0, A, WT, m0, n0, 2, tid); CP_COMMIT();
    CP_WAIT(1); __syncthreads();
    compute_tile(sb1, sb1 + 16384, acc, wm, wn, lane);
    CP_WAIT(0); __syncthreads();
    compute_tile(sb0, sb0 + 16384, acc, wm, wn, lane);

#pragma unroll
    for (int mt = 0; mt < 2; mt++) {
#pragma unroll
        for (int nt = 0; nt < 4; nt++) {
            const int row = m0 + wm * 32 + mt * 16 + grp;
            const int col = n0 + wn * 32 + nt * 8 + quad * 2;
            float b0 = 0.f, b1 = 0.f;
            if (bias) { b0 = bias[col]; b1 = bias[col + 1]; }
            store2(C, (size_t)row * N + col,
                   acc[mt][nt][0] + b0, acc[mt][nt][1] + b1);
            store2(C, (size_t)(row + 8) * N + col,
                   acc[mt][nt][2] + b0, acc[mt][nt][3] + b1);
        }
    }
}

// ---------------------------------------------------------------------------
// Converters (once per call, bandwidth-bound)
// ---------------------------------------------------------------------------
__global__ void conv_f32_f16(const float* __restrict__ in,
                             __half* __restrict__ out, int n4)
{
    const int i = blockIdx.x * 256 + threadIdx.x;
    if (i < n4) {
        const float4 v = reinterpret_cast<const float4*>(in)[i];
        uint2 o;
        o.x = packh2(v.x, v.y);
        o.y = packh2(v.z, v.w);
        reinterpret_cast<uint2*>(out)[i] = o;
    }
}

__global__ void conv_transpose2(const float* __restrict__ w1, __half* __restrict__ wt1,
                                const float* __restrict__ w2, __half* __restrict__ wt2)
{
    const int i = blockIdx.x * 256 + threadIdx.x;
    const int n1 = KDIM * QKV_N;
    if (i < n1) {
        const int k = i / QKV_N, n = i % QKV_N;
        wt1[(size_t)n * KDIM + k] = __float2half(w1[i]);
    } else if (i < n1 + KDIM * C_DIM) {
        const int j = i - n1;
        const int k = j / C_DIM, n = j % C_DIM;
        wt2[(size_t)n * KDIM + k] = __float2half(w2[j]);
    }
}

// ---------------------------------------------------------------------------
// Tensor-core attention v6: grid (4096 windows, 6 heads), 64 threads.
// cp.async Q/K staging (R16-validated). PV A-fragments pre-packed to free
// the s[] registers before O accumulation -> lower peak regs, 10 CTAs/SM.
// ---------------------------------------------------------------------------
#define HEADW 3712

__global__ __launch_bounds__(64, 10)
void attn_kernel(const float* __restrict__ mask)
{
    __shared__ uint32_t smw[HEADW];     // 14848 B
    const int b  = blockIdx.x;
    const int gh = blockIdx.y;
    const int tid = threadIdx.x;
    const __half* qkv = reinterpret_cast<const __half*>(g_qkv_h);
    __half* attout = reinterpret_cast<__half*>(g_att_h);
    const uint32_t sbase = smem_u32(smw);

    // ---- Q/K staging via cp.async: 392 16B tasks ----
    for (int f = tid; f < 392; f += 64) {
        const int sel = f / 196, r2 = f % 196;
        const int i = r2 >> 2, c = r2 & 3;
        CP_ASYNC16(sbase + (sel * 1280 + i * 20 + c * 4) * 4,
                   qkv + ((size_t)b * NTOK + i) * QKV_N + sel * C_DIM + gh * 32 + c * 8);
    }
    CP_COMMIT();

    // ---- V transpose (LDG overlaps cp.async DMA): 128 tasks ----
    for (int f = tid; f < 128; f += 64) {
        const int jp = f >> 2, dq = f & 3;
        uint4 lo4 = make_uint4(0, 0, 0, 0), hi4 = make_uint4(0, 0, 0, 0);
        const __half* basep = qkv + ((size_t)b * NTOK + 2 * jp) * QKV_N
                              + 2 * C_DIM + gh * 32 + dq * 8;
        if (2 * jp     < NTOK) lo4 = *reinterpret_cast<const uint4*>(basep);
        if (2 * jp + 1 < NTOK) hi4 = *reinterpret_cast<const uint4*>(basep + QKV_N);
        const __half* lo = reinterpret_cast<const __half*>(&lo4);
        const __half* hi = reinterpret_cast<const __half*>(&hi4);
        uint32_t* Vh = smw + 2560;
#pragma unroll
        for (int t = 0; t < 8; t++) {
            __half2 hv = __halves2half2(lo[t], hi[t]);
            Vh[(dq * 8 + t) * 36 + jp] = *reinterpret_cast<uint32_t*>(&hv);
        }
    }
    CP_WAIT(0);
    __syncthreads();

    const int wid = tid >> 5, lane = tid & 31;
    const int g = lane >> 2, q = lane & 3;
    const int rowbase = wid * 32;
    const uint32_t* Qs = smw;
    const uint32_t* Ks = smw + 1280;
    const uint32_t* Vt = smw + 2560;

    // ---- S = Q K^T : 2 m-tiles x 8 n-tiles ----
    float s[2][8][4] = {};
#pragma unroll
    for (int ks = 0; ks < 2; ks++) {
        uint32_t a[2][4];
#pragma unroll
        for (int mtl = 0; mtl < 2; mtl++) {
            const int r = rowbase + mtl * 16 + g;
            a[mtl][0] = Qs[r * 20 + 8 * ks + q];
            a[mtl][1] = Qs[(r + 8) * 20 + 8 * ks + q];
            a[mtl][2] = Qs[r * 20 + 8 * ks + q + 4];
            a[mtl][3] = Qs[(r + 8) * 20 + 8 * ks + q + 4];
        }
#pragma unroll
        for (int nt = 0; nt < 8; nt++) {
            uint32_t bb[2];
            bb[0] = Ks[(8 * nt + g) * 20 + 8 * ks + q];
            bb[1] = Ks[(8 * nt + g) * 20 + 8 * ks + q + 4];
            mma_f16(s[0][nt], a[0], bb);
            mma_f16(s[1][nt], a[1], bb);
        }
    }

    // ---- scale + mask from global (L2-resident); invalid cols -> -1e30 ----
    const float scale = 0.17677669529663687f;
    const float* mrow = mask + (size_t)(b & (NWIN - 1)) * NTOK * NTOK;
#pragma unroll
    for (int mtl = 0; mtl < 2; mtl++) {
        const int r1 = rowbase + mtl * 16 + g;
        const float* m1 = mrow + min(r1, 48) * NTOK;
        const float* m2 = mrow + min(r1 + 8, 48) * NTOK;
#pragma unroll
        for (int nt = 0; nt < 8; nt++) {
            const int j0 = 8 * nt + 2 * q, j1 = j0 + 1;
            if (j0 < NTOK) {
                s[mtl][nt][0] = fmaf(s[mtl][nt][0], scale, m1[j0]);
                s[mtl][nt][2] = fmaf(s[mtl][nt][2], scale, m2[j0]);
            } else { s[mtl][nt][0] = -1e30f; s[mtl][nt][2] = -1e30f; }
            if (j1 < NTOK) {
                s[mtl][nt][1] = fmaf(s[mtl][nt][1], scale, m1[j1]);
                s[mtl][nt][3] = fmaf(s[mtl][nt][3], scale, m2[j1]);
            } else { s[mtl][nt][1] = -1e30f; s[mtl][nt][3] = -1e30f; }
        }
    }

    // ---- fragment softmax (shfl xor 1,2 within lane quads) ----
#pragma unroll
    for (int mtl = 0; mtl < 2; mtl++) {
        float mxA = -1e30f, mxB = -1e30f;
#pragma unroll
        for (int nt = 0; nt < 8; nt++) {
            mxA = fmaxf(mxA, fmaxf(s[mtl][nt][0], s[mtl][nt][1]));
            mxB = fmaxf(mxB, fmaxf(s[mtl][nt][2], s[mtl][nt][3]));
        }
        mxA = fmaxf(mxA, __shfl_xor_sync(0xFFFFFFFFu, mxA, 1));
        mxA = fmaxf(mxA, __shfl_xor_sync(0xFFFFFFFFu, mxA, 2));
        mxB = fmaxf(mxB, __shfl_xor_sync(0xFFFFFFFFu, mxB, 1));
        mxB = fmaxf(mxB, __shfl_xor_sync(0xFFFFFFFFu, mxB, 2));
        float sA = 0.f, sB = 0.f;
#pragma unroll
        for (int nt = 0; nt < 8; nt++) {
            s[mtl][nt][0] = __expf(s[mtl][nt][0] - mxA); sA += s[mtl][nt][0];
            s[mtl][nt][1] = __expf(s[mtl][nt][1] - mxA); sA += s[mtl][nt][1];
            s[mtl][nt][2] = __expf(s[mtl][nt][2] - mxB); sB += s[mtl][nt][2];
            s[mtl][nt][3] = __expf(s[mtl][nt][3] - mxB); sB += s[mtl][nt][3];
        }
        sA += __shfl_xor_sync(0xFFFFFFFFu, sA, 1);
        sA += __shfl_xor_sync(0xFFFFFFFFu, sA, 2);
        sB += __shfl_xor_sync(0xFFFFFFFFu, sB, 1);
        sB += __shfl_xor_sync(0xFFFFFFFFu, sB, 2);
        const float invA = 1.0f / sA, invB = 1.0f / sB;
#pragma unroll
        for (int nt = 0; nt < 8; nt++) {
            s[mtl][nt][0] *= invA; s[mtl][nt][1] *= invA;
            s[mtl][nt][2] *= invB; s[mtl][nt][3] *= invB;
        }
    }

    // ---- pack ALL PV A-frags first (frees s before O accumulation) ----
    uint32_t pa[4][2][4];
#pragma unroll
    for (int ks = 0; ks < 4; ks++) {
#pragma unroll
        for (int mtl = 0; mtl < 2; mtl++) {
            pa[ks][mtl][0] = packh2(s[mtl][2 * ks][0],     s[mtl][2 * ks][1]);
            pa[ks][mtl][1] = packh2(s[mtl][2 * ks][2],     s[mtl][2 * ks][3]);
            pa[ks][mtl][2] = packh2(s[mtl][2 * ks + 1][0], s[mtl][2 * ks + 1][1]);
            pa[ks][mtl][3] = packh2(s[mtl][2 * ks + 1][2], s[mtl][2 * ks + 1][3]);
        }
    }

    // ---- O = P V ----
    float o[2][4][4] = {};
#pragma unroll
    for (int ks = 0; ks < 4; ks++) {
#pragma unroll
        for (int nt2 = 0; nt2 < 4; nt2++) {
            uint32_t bb[2];
            bb[0] = Vt[(8 * nt2 + g) * 36 + 8 * ks + q];
            bb[1] = Vt[(8 * nt2 + g) * 36 + 8 * ks + q + 4];
            mma_f16(o[0][nt2], pa[ks][0], bb);
            mma_f16(o[1][nt2], pa[ks][1], bb);
        }
    }

    // ---- store valid rows as fp16 ----
#pragma unroll
    for (int mtl = 0; mtl < 2; mtl++) {
        const int r1 = rowbase + mtl * 16 + g, r2 = r1 + 8;
#pragma unroll
        for (int nt2 = 0; nt2 < 4; nt2++) {
            const int col = gh * 32 + 8 * nt2 + 2 * q;
            if (r1 < NTOK)
                *reinterpret_cast<uint32_t*>(
                    attout + ((size_t)b * NTOK + r1) * C_DIM + col) =
                    packh2(o[mtl][nt2][0], o[mtl][nt2][1]);
            if (r2 < NTOK)
                *reinterpret_cast<uint32_t*>(
                    attout + ((size_t)b * NTOK + r2) * C_DIM + col) =
                    packh2(o[mtl][nt2][2], o[mtl][nt2][3]);
        }
    }
}

// ---------------------------------------------------------------------------
// Launch pipeline
// ---------------------------------------------------------------------------
extern "C" void kernel_launch(void* const* d_in, const int* in_sizes, int n_in,
                              void* d_out, int out_size)
{
    const float* x      = (const float*)d_in[0];
    const float* mask   = (const float*)d_in[1];
    const float* w_qkv  = (const float*)d_in[2];
    const float* w_proj = (const float*)d_in[3];
    const float* b_proj = (const float*)d_in[4];
    float* out = (float*)d_out;

    void *xh_r, *qkv_r, *att_r, *wq_r, *wp_r;
    cudaGetSymbolAddress(&xh_r,  g_x_h);
    cudaGetSymbolAddress(&qkv_r, g_qkv_h);
    cudaGetSymbolAddress(&att_r, g_att_h);
    cudaGetSymbolAddress(&wq_r,  g_wqkvT_h);
    cudaGetSymbolAddress(&wp_r,  g_wprojT_h);
    __half* xh    = (__half*)xh_r;
    __half* qkvp  = (__half*)qkv_r;
    __half* attp  = (__half*)att_r;
    __half* wqkvT = (__half*)wq_r;
    __half* wprojT = (__half*)wp_r;

    cudaFuncSetAttribute(mma_gemm<__half>,
                         cudaFuncAttributeMaxDynamicSharedMemorySize, GEMM_SMEM);
    cudaFuncSetAttribute(mma_gemm<float>,
                         cudaFuncAttributeMaxDynamicSharedMemorySize, GEMM_SMEM);

    // One-time conversions
    const int n4 = M_TOTAL * KDIM / 4;
    conv_f32_f16<<<(n4 + 255) / 256, 256>>>(x, xh, n4);
    const int nt2 = KDIM * QKV_N + KDIM * C_DIM;
    conv_transpose2<<<(nt2 + 255) / 256, 256>>>(w_qkv, wqkvT, w_proj, wprojT);

    // QKV: [200704,192] @ [192,576] -> fp16
    mma_gemm<__half><<<dim3(QKV_N / BN, M_TOTAL / BM), 256, GEMM_SMEM>>>(
        xh, wqkvT, qkvp, nullptr, QKV_N);

    // Attention: (window, head) grid, 64-thread CTAs
    attn_kernel<<<dim3(B_WIN, NHEAD), 64>>>(mask);

    // Proj: [200704,192] @ [192,192] + bias -> fp32 output
    mma_gemm<float><<<dim3(C_DIM / BN, M_TOTAL / BM), 256, GEMM_SMEM>>>(
        attp, wprojT, out, b_proj, C_DIM);
}